// round 17
// baseline (speedup 1.0000x reference)
#include <cuda_runtime.h>
#include <cuda_fp16.h>
#include <math.h>
#include <stdint.h>

// Problem constants
#define N_NODES   80000
#define N_EDGES   160000
#define HALF_E    80000
#define HID       300
#define NODE_DIM  133
#define EDGE_DIM  14
#define N_GRAPHS  1600
#define NN        300

// ---------------------------------------------------------------------------
// Device scratch
// ---------------------------------------------------------------------------
__device__ float g_h[(size_t)N_EDGES * HID];
__device__ float g_h2[(size_t)N_EDGES * HID];
__device__ float g_h3[(size_t)N_EDGES * HID];
__device__ float g_h4[(size_t)N_EDGES * HID];
__device__ float g_nacc[(size_t)N_NODES * HID];
__device__ float g_nacc2[(size_t)N_NODES * HID];
__device__ float g_shared[(size_t)N_NODES * HID];
__device__ float g_mu[(size_t)N_NODES * HID];
__device__ float g_lv[(size_t)N_NODES * HID];

// pre-split A operand buffers (packed fp16 pairs; hi/lo), 2 sets for z-fusion
#define AWORDS 25600000   // >= 160000*160 and >= 80000*304
__device__ __align__(256) uint32_t g_ah0[AWORDS];
__device__ __align__(256) uint32_t g_al0[AWORDS];
__device__ __align__(256) uint32_t g_ah1[AWORDS];
__device__ __align__(256) uint32_t g_al1[AWORDS];
// pre-split transposed weights [n=320][kw-pitch]
#define WWORDS 900000
__device__ __align__(256) uint32_t g_wh[WWORDS];
__device__ __align__(256) uint32_t g_wl[WWORDS];

__device__ int g_src[N_EDGES];
__device__ int g_dst[N_EDGES];
__device__ int g_deg[N_NODES];
__device__ int g_rowptr[N_NODES + 1];
__device__ int g_cursor[N_NODES];
__device__ int g_eidx[N_EDGES];
__device__ int g_gcnt[N_GRAPHS];
__device__ int g_gptr[N_GRAPHS + 1];

// ---------------------------------------------------------------------------
// Setup kernels
// ---------------------------------------------------------------------------
__global__ void k_zero_all(int* deg, int* gcnt) {
    int i = blockIdx.x * blockDim.x + threadIdx.x;
    if (i < N_NODES) deg[i] = 0;
    if (i < N_GRAPHS) gcnt[i] = 0;
}

__global__ void k_setup(const int* __restrict__ sh, const int* __restrict__ dh,
                        const int* __restrict__ batch,
                        int* __restrict__ src, int* __restrict__ dst,
                        int* __restrict__ deg, int* __restrict__ gcnt) {
    int i = blockIdx.x * blockDim.x + threadIdx.x;
    if (i < HALF_E) {
        int s = sh[i], d = dh[i];
        src[i] = s;          dst[i] = d;
        src[i + HALF_E] = d; dst[i + HALF_E] = s;
        atomicAdd(&deg[d], 1);
        atomicAdd(&deg[s], 1);
    }
    if (i < N_NODES) atomicAdd(&gcnt[batch[i]], 1);
}

__device__ void scan_block(const int* __restrict__ in, int* __restrict__ out,
                           int* __restrict__ copy, int n) {
    __shared__ int sums[1024];
    int t = threadIdx.x;
    int chunk = (n + 1023) / 1024;
    int s = t * chunk;
    int e = s + chunk; if (e > n) e = n; if (s > n) s = n;
    int local = 0;
    for (int i = s; i < e; i++) local += in[i];
    sums[t] = local;
    __syncthreads();
    if (t == 0) {
        int run = 0;
        for (int i = 0; i < 1024; i++) { int v = sums[i]; sums[i] = run; run += v; }
        out[n] = run;
    }
    __syncthreads();
    int run = sums[t];
    for (int i = s; i < e; i++) {
        out[i] = run;
        if (copy) copy[i] = run;
        run += in[i];
    }
}

__global__ void k_scan2(const int* deg, int* rowptr, int* cursor,
                        const int* gcnt, int* gptr) {
    if (blockIdx.x == 0) scan_block(deg, rowptr, cursor, N_NODES);
    else                 scan_block(gcnt, gptr, nullptr, N_GRAPHS);
}

__global__ void k_fill_csr(const int* __restrict__ dst, int* __restrict__ cursor,
                           int* __restrict__ eidx, int n) {
    int e = blockIdx.x * blockDim.x + threadIdx.x;
    if (e < n) {
        int p = atomicAdd(&cursor[dst[e]], 1);
        eidx[p] = e;
    }
}

// dual segment-sum, 2 nodes per block, float2 lanes (used for au stage only)
__global__ void k_segsum(const float* __restrict__ h0, float* __restrict__ o0,
                         const float* __restrict__ h1, float* __restrict__ o1,
                         const int* __restrict__ rowptr, const int* __restrict__ eidx) {
    const float* h = blockIdx.y ? h1 : h0;
    float* o       = blockIdx.y ? o1 : o0;
    int node = blockIdx.x * 2 + (threadIdx.x >= 160 ? 1 : 0);
    int j = threadIdx.x % 160;        // float2 index
    if (j >= NN / 2) return;
    int s = rowptr[node], e = rowptr[node + 1];
    float s0 = 0.f, s1 = 0.f;
    for (int i = s; i < e; i++) {
        const float2 v = *(const float2*)&h[(size_t)eidx[i] * NN + 2 * j];
        s0 += v.x; s1 += v.y;
    }
    *(float2*)&o[(size_t)node * NN + 2 * j] = make_float2(s0, s1);
}

// ---------------------------------------------------------------------------
// fp16 split-pack helpers
// ---------------------------------------------------------------------------
__device__ __forceinline__ void splitpack(float v0, float v1,
                                          uint32_t& hi, uint32_t& lo) {
    __half h0 = __float2half_rn(v0), h1 = __float2half_rn(v1);
    __half l0 = __float2half_rn(v0 - __half2float(h0));
    __half l1 = __float2half_rn(v1 - __half2float(h1));
    hi = (uint32_t)__half_as_ushort(h0) | ((uint32_t)__half_as_ushort(h1) << 16);
    lo = (uint32_t)__half_as_ushort(l0) | ((uint32_t)__half_as_ushort(l1) << 16);
}

// ---------------------------------------------------------------------------
// FUSED segsum + aggsplit (mp iterations; nacc never materialized).
// For node n with incoming edges {ei}: nacc = sum h[ei].
// Outgoing edges of n are rev(ei), and agg[rev(ei)] = nacc - h[ei].
// Pass 1 sums (reads h[ei]); pass 2 re-reads h[ei] (L1-hot) and writes the
// packed split row at rev(ei). Two nodes per 320-thread block; lane j is
// float2 column pair (j<150), lanes 150-159 write zero padding words.
// ---------------------------------------------------------------------------
__global__ void k_segagg(const float* __restrict__ h0,
                         uint32_t* __restrict__ AH0, uint32_t* __restrict__ AL0,
                         const float* __restrict__ h1,
                         uint32_t* __restrict__ AH1, uint32_t* __restrict__ AL1,
                         const int* __restrict__ rowptr, const int* __restrict__ eidx) {
    const float* h = blockIdx.y ? h1 : h0;
    uint32_t* AH   = blockIdx.y ? AH1 : AH0;
    uint32_t* AL   = blockIdx.y ? AL1 : AL0;
    const int node = blockIdx.x * 2 + (threadIdx.x >= 160 ? 1 : 0);
    const int j = threadIdx.x % 160;
    const int s = rowptr[node], e = rowptr[node + 1];

    float s0 = 0.f, s1 = 0.f;
    if (j < NN / 2) {
        for (int i = s; i < e; i++) {
            const float2 v = *(const float2*)&h[(size_t)eidx[i] * NN + 2 * j];
            s0 += v.x; s1 += v.y;
        }
    }
    for (int i = s; i < e; i++) {
        const int ei = eidx[i];
        const int re = (ei < HALF_E) ? ei + HALF_E : ei - HALF_E;
        uint32_t hi = 0u, lo = 0u;
        if (j < NN / 2) {
            const float2 v = *(const float2*)&h[(size_t)ei * NN + 2 * j];
            splitpack(s0 - v.x, s1 - v.y, hi, lo);
        }
        AH[(size_t)re * 160 + j] = hi;
        AL[(size_t)re * 160 + j] = lo;
    }
}

// ---- all-weights pre-split in ONE launch ----
struct WJob { const float* W; int K; int pitch; int woff; };
struct WJobs { WJob j[15]; };

__global__ void k_splitw_all(WJobs jobs, uint32_t* __restrict__ WH,
                             uint32_t* __restrict__ WL) {
    WJob jb = jobs.j[blockIdx.y];
    int n = blockIdx.x;        // 0..319
    int kw = threadIdx.x;
    if (kw >= jb.pitch) return;
    float v0 = 0.f, v1 = 0.f;
    if (n < NN) {
        int k0 = 2 * kw;
        if (k0 < jb.K)     v0 = jb.W[(size_t)k0 * NN + n];
        if (k0 + 1 < jb.K) v1 = jb.W[(size_t)(k0 + 1) * NN + n];
    }
    uint32_t hi, lo;
    splitpack(v0, v1, hi, lo);
    WH[(size_t)jb.woff + (size_t)n * jb.pitch + kw] = hi;
    WL[(size_t)jb.woff + (size_t)n * jb.pitch + kw] = lo;
}

// ---- concat pre-split: A[r] = [X[idx[r]?][0:d1], Y[r][0:d2]] -> packed ----
// 2D block: threadIdx.x = kw, threadIdx.y = row-in-block.
__global__ void k_catsplit(const float* __restrict__ X0, const float* __restrict__ Y0,
                           uint32_t* __restrict__ AH0, uint32_t* __restrict__ AL0,
                           const float* __restrict__ X1, const float* __restrict__ Y1,
                           uint32_t* __restrict__ AH1, uint32_t* __restrict__ AL1,
                           const int* __restrict__ idx, int K, int d1, int d2,
                           int pitch) {
    const float* X = blockIdx.y ? X1 : X0;
    const float* Y = blockIdx.y ? Y1 : Y0;
    uint32_t* AH   = blockIdx.y ? AH1 : AH0;
    uint32_t* AL   = blockIdx.y ? AL1 : AL0;
    int r  = blockIdx.x * blockDim.y + threadIdx.y;
    int kw = threadIdx.x;     // 0..pitch-1
    size_t bx = (size_t)(idx ? idx[r] : r) * d1;
    float v[2];
#pragma unroll
    for (int u = 0; u < 2; u++) {
        int k = 2 * kw + u;
        float t = 0.f;
        if (k < K) t = (k < d1) ? X[bx + k] : Y[(size_t)r * d2 + (k - d1)];
        v[u] = t;
    }
    uint32_t hi, lo;
    splitpack(v[0], v[1], hi, lo);
    AH[(size_t)r * pitch + kw] = hi;
    AL[(size_t)r * pitch + kw] = lo;
}

// ---------------------------------------------------------------------------
// cp.async helpers
// ---------------------------------------------------------------------------
__device__ __forceinline__ void cpa16(uint32_t dst, const void* src) {
    asm volatile("cp.async.cg.shared.global [%0], [%1], 16;"
                 :: "r"(dst), "l"(src));
}
#define CPA_COMMIT() asm volatile("cp.async.commit_group;" ::: "memory")
#define CPA_WAIT(N)  asm volatile("cp.async.wait_group %0;" :: "n"(N) : "memory")

__device__ __forceinline__ void mma16(float* c, const uint32_t* a,
                                      const uint32_t* b) {
    asm volatile(
        "mma.sync.aligned.m16n8k16.row.col.f32.f16.f16.f32 "
        "{%0,%1,%2,%3}, {%4,%5,%6,%7}, {%8,%9}, {%0,%1,%2,%3};\n"
        : "+f"(c[0]), "+f"(c[1]), "+f"(c[2]), "+f"(c[3])
        : "r"(a[0]), "r"(a[1]), "r"(a[2]), "r"(a[3]), "r"(b[0]), "r"(b[1]));
}

// ---------------------------------------------------------------------------
// Pure cp.async fp16x3-split GEMM, 3-stage pipeline.
// C = act( A @ W + bias (+ Cin) ).  Block 128x64, BK=32 (16 words), 256 thr.
// ---------------------------------------------------------------------------
#define PW 20
#define BUFW 7680            // words per buffer
#define NSTAGE 3
#define DSMB (NSTAGE * BUFW * 4)   // 92160 bytes

template <bool RELU, bool ADD_C>
__global__ __launch_bounds__(256, 2)
void k_gemm(const uint32_t* __restrict__ AH0, const uint32_t* __restrict__ AL0,
            const float* __restrict__ Cin0, float* __restrict__ Cout0,
            const float* __restrict__ bias0, int woff0,
            const uint32_t* __restrict__ AH1, const uint32_t* __restrict__ AL1,
            const float* __restrict__ Cin1, float* __restrict__ Cout1,
            const float* __restrict__ bias1, int woff1,
            const uint32_t* __restrict__ WHb, const uint32_t* __restrict__ WLb,
            int pitch, int nc) {
    extern __shared__ uint32_t dsm[];
    const uint32_t sb = (uint32_t)__cvta_generic_to_shared(dsm);

    const uint32_t* AH = blockIdx.z ? AH1 : AH0;
    const uint32_t* AL = blockIdx.z ? AL1 : AL0;
    const float* Cin   = blockIdx.z ? Cin1 : Cin0;
    float* Cout        = blockIdx.z ? Cout1 : Cout0;
    const float* bias  = blockIdx.z ? bias1 : bias0;
    const uint32_t* WH = WHb + (blockIdx.z ? woff1 : woff0);
    const uint32_t* WL = WLb + (blockIdx.z ? woff1 : woff0);

    const int tid  = threadIdx.x;
    const int warp = tid >> 5;
    const int lane = tid & 31;
    const int wm = (warp >> 1) * 32;
    const int wn = (warp & 1) * 32;
    const int row0 = blockIdx.y * 128;
    const int col0 = blockIdx.x * 64;
    const int lq = lane >> 2;
    const int lr = lane & 3;

    auto issue = [&](int c) {
        const int bb = (c % NSTAGE) * BUFW;
        const int cw = c * 16;
#pragma unroll
        for (int i = 0; i < 4; i++) {       // A: 1024 x 16B
            int o = tid + 256 * i;
            int half = o >> 9, rem = o & 511, r = rem >> 2, ch = rem & 3;
            const uint32_t* s = (half ? AL : AH) +
                                (size_t)(row0 + r) * pitch + cw + ch * 4;
            uint32_t d = sb + (bb + half * 2560 + r * PW + ch * 4) * 4;
            cpa16(d, s);
        }
#pragma unroll
        for (int i = 0; i < 2; i++) {       // B: 512 x 16B
            int o = tid + 256 * i;
            int half = o >> 8, rem = o & 255, n = rem >> 2, ch = rem & 3;
            const uint32_t* s = (half ? WL : WH) +
                                (size_t)(col0 + n) * pitch + cw + ch * 4;
            uint32_t d = sb + (bb + 5120 + half * 1280 + n * PW + ch * 4) * 4;
            cpa16(d, s);
        }
    };

    float acc[2][4][4];
#pragma unroll
    for (int mf = 0; mf < 2; mf++)
#pragma unroll
        for (int nf = 0; nf < 4; nf++)
#pragma unroll
            for (int i = 0; i < 4; i++) acc[mf][nf][i] = 0.f;

    issue(0); CPA_COMMIT();
    if (nc > 1) { issue(1); CPA_COMMIT(); }

    for (int c = 0; c < nc; c++) {
        if (c + 1 < nc) { CPA_WAIT(1); }
        else            { CPA_WAIT(0); }
        __syncthreads();
        if (c + 2 < nc) { issue(c + 2); CPA_COMMIT(); }

        const uint32_t* buf  = dsm + (c % NSTAGE) * BUFW;
        const uint32_t* AsHi = buf;
        const uint32_t* AsLo = buf + 2560;
        const uint32_t* BsHi = buf + 5120;
        const uint32_t* BsLo = buf + 6400;

#pragma unroll
        for (int s = 0; s < 2; s++) {
            const int wb = s * 8;
            uint32_t ahi[2][4], alo[2][4];
#pragma unroll
            for (int mf = 0; mf < 2; mf++) {
                const int r0 = (wm + mf * 16 + lq) * PW;
                const int r8 = r0 + 8 * PW;
                ahi[mf][0] = AsHi[r0 + wb + lr];
                ahi[mf][1] = AsHi[r8 + wb + lr];
                ahi[mf][2] = AsHi[r0 + wb + lr + 4];
                ahi[mf][3] = AsHi[r8 + wb + lr + 4];
                alo[mf][0] = AsLo[r0 + wb + lr];
                alo[mf][1] = AsLo[r8 + wb + lr];
                alo[mf][2] = AsLo[r0 + wb + lr + 4];
                alo[mf][3] = AsLo[r8 + wb + lr + 4];
            }
            uint32_t bhi[4][2], blo[4][2];
#pragma unroll
            for (int nf = 0; nf < 4; nf++) {
                const int nb = (wn + nf * 8 + lq) * PW;
                bhi[nf][0] = BsHi[nb + wb + lr];
                bhi[nf][1] = BsHi[nb + wb + lr + 4];
                blo[nf][0] = BsLo[nb + wb + lr];
                blo[nf][1] = BsLo[nb + wb + lr + 4];
            }
#pragma unroll
            for (int mf = 0; mf < 2; mf++)
#pragma unroll
                for (int nf = 0; nf < 4; nf++)
                    mma16(acc[mf][nf], ahi[mf], bhi[nf]);
#pragma unroll
            for (int mf = 0; mf < 2; mf++)
#pragma unroll
                for (int nf = 0; nf < 4; nf++)
                    mma16(acc[mf][nf], ahi[mf], blo[nf]);
#pragma unroll
            for (int mf = 0; mf < 2; mf++)
#pragma unroll
                for (int nf = 0; nf < 4; nf++)
                    mma16(acc[mf][nf], alo[mf], bhi[nf]);
        }
    }

    // epilogue
#pragma unroll
    for (int mf = 0; mf < 2; mf++) {
#pragma unroll
        for (int nf = 0; nf < 4; nf++) {
            int c = col0 + wn + nf * 8 + 2 * lr;
            if (c >= NN) continue;
            float b0 = bias[c], b1 = bias[c + 1];
#pragma unroll
            for (int half = 0; half < 2; half++) {
                int r = row0 + wm + mf * 16 + lq + half * 8;
                float v0 = acc[mf][nf][half * 2 + 0] + b0;
                float v1 = acc[mf][nf][half * 2 + 1] + b1;
                if (ADD_C) {
                    const float2 ci = *(const float2*)&Cin[(size_t)r * NN + c];
                    v0 += ci.x; v1 += ci.y;
                }
                if (RELU) { v0 = fmaxf(v0, 0.f); v1 = fmaxf(v1, 0.f); }
                *(float2*)&Cout[(size_t)r * NN + c] = make_float2(v0, v1);
            }
        }
    }
}

// ---------------------------------------------------------------------------
// Final pooling
// ---------------------------------------------------------------------------
__global__ void k_pool(const float* __restrict__ mu, const float* __restrict__ lv,
                       const float* __restrict__ w, const float* __restrict__ eps,
                       const int* __restrict__ gptr, float* __restrict__ out) {
    int g = blockIdx.x;
    int j = threadIdx.x;
    if (j >= NN) return;
    int s = gptr[g], e = gptr[g + 1];
    float ms = 0.f, ls = 0.f;
    for (int n = s; n < e; n++) {
        float ww = w[n];
        ms += mu[(size_t)n * NN + j] * ww;
        ls += lv[(size_t)n * NN + j] * ww;
    }
    float c = fmaxf((float)(e - s), 1.f);
    out[(size_t)g * NN + j] = ms / c + expf(0.5f * ls / c) * eps[(size_t)g * NN + j];
}

// ---------------------------------------------------------------------------
// Host orchestration
// ---------------------------------------------------------------------------
static void* sym(const void* s) {
    void* p = nullptr;
    cudaGetSymbolAddress(&p, (const void*)s);
    return p;
}

// weight-buffer offsets (words) and pitches
#define P_LIN_T  80
#define P_300    160
#define P_AU_T   224
#define P_AU_MLV 304
#define OFF_T_LIN   0
#define OFF_T_MP    25600
#define OFF_T_AU    179200
#define OFF_MU_LIN  250880
#define OFF_MU_MP   302080
#define OFF_MU_AU   455680
#define OFF_LV_LIN  552960
#define OFF_LV_MP   604160
#define OFF_LV_AU   757760

extern "C" void kernel_launch(void* const* d_in, const int* in_sizes, int n_in,
                              void* d_out, int out_size) {
    const float* x         = (const float*)d_in[0];
    const float* edge_attr = (const float*)d_in[1];
    const float* W_atoms   = (const float*)d_in[2];
    const float* eps       = (const float*)d_in[3];
    const int*   src_half  = (const int*)d_in[4];
    const int*   dst_half  = (const int*)d_in[5];
    const int*   batch     = (const int*)d_in[6];
    const float* t_lin_w   = (const float*)d_in[7];
    const float* t_lin_b   = (const float*)d_in[8];
    const float* t_mp_w    = (const float*)d_in[9];
    const float* t_mp_b    = (const float*)d_in[10];
    const float* t_au_w    = (const float*)d_in[11];
    const float* t_au_b    = (const float*)d_in[12];
    const float* mu_lin_w  = (const float*)d_in[13];
    const float* mu_lin_b  = (const float*)d_in[14];
    const float* mu_mp_w   = (const float*)d_in[15];
    const float* mu_mp_b   = (const float*)d_in[16];
    const float* mu_au_w   = (const float*)d_in[17];
    const float* mu_au_b   = (const float*)d_in[18];
    const float* lv_lin_w  = (const float*)d_in[19];
    const float* lv_lin_b  = (const float*)d_in[20];
    const float* lv_mp_w   = (const float*)d_in[21];
    const float* lv_mp_b   = (const float*)d_in[22];
    const float* lv_au_w   = (const float*)d_in[23];
    const float* lv_au_b   = (const float*)d_in[24];
    float* out = (float*)d_out;
    (void)in_sizes; (void)n_in; (void)out_size;

    float* h     = (float*)sym(g_h);
    float* h2    = (float*)sym(g_h2);
    float* h3    = (float*)sym(g_h3);
    float* h4    = (float*)sym(g_h4);
    float* nacc  = (float*)sym(g_nacc);
    float* nacc2 = (float*)sym(g_nacc2);
    float* shrd  = (float*)sym(g_shared);
    float* mu    = (float*)sym(g_mu);
    float* lv    = (float*)sym(g_lv);
    uint32_t* ah0 = (uint32_t*)sym(g_ah0);
    uint32_t* al0 = (uint32_t*)sym(g_al0);
    uint32_t* ah1 = (uint32_t*)sym(g_ah1);
    uint32_t* al1 = (uint32_t*)sym(g_al1);
    uint32_t* wh  = (uint32_t*)sym(g_wh);
    uint32_t* wl  = (uint32_t*)sym(g_wl);
    int* src    = (int*)sym(g_src);
    int* dst    = (int*)sym(g_dst);
    int* deg    = (int*)sym(g_deg);
    int* rowptr = (int*)sym(g_rowptr);
    int* cursor = (int*)sym(g_cursor);
    int* eidx   = (int*)sym(g_eidx);
    int* gcnt   = (int*)sym(g_gcnt);
    int* gptr   = (int*)sym(g_gptr);

    cudaFuncSetAttribute(k_gemm<true,  false>, cudaFuncAttributeMaxDynamicSharedMemorySize, DSMB);
    cudaFuncSetAttribute(k_gemm<true,  true >, cudaFuncAttributeMaxDynamicSharedMemorySize, DSMB);
    cudaFuncSetAttribute(k_gemm<false, false>, cudaFuncAttributeMaxDynamicSharedMemorySize, DSMB);

    const int TPB = 256;

    // ---- setup ----
    k_zero_all<<<(N_NODES + TPB - 1) / TPB, TPB>>>(deg, gcnt);
    k_setup<<<(N_NODES + TPB - 1) / TPB, TPB>>>(src_half, dst_half, batch,
                                                src, dst, deg, gcnt);

    // ---- all weights pre-split in one launch ----
    {
        WJobs jobs;
        int ji = 0;
        jobs.j[ji++] = {t_lin_w, NODE_DIM + EDGE_DIM, P_LIN_T, OFF_T_LIN};
        for (int i = 0; i < 3; i++)
            jobs.j[ji++] = {t_mp_w + (size_t)i * HID * HID, HID, P_300, OFF_T_MP + i * 51200};
        jobs.j[ji++] = {t_au_w, NODE_DIM + HID, P_AU_T, OFF_T_AU};
        jobs.j[ji++] = {mu_lin_w, HID + EDGE_DIM, P_300, OFF_MU_LIN};
        for (int i = 0; i < 3; i++)
            jobs.j[ji++] = {mu_mp_w + (size_t)i * HID * HID, HID, P_300, OFF_MU_MP + i * 51200};
        jobs.j[ji++] = {mu_au_w, 2 * HID, P_AU_MLV, OFF_MU_AU};
        jobs.j[ji++] = {lv_lin_w, HID + EDGE_DIM, P_300, OFF_LV_LIN};
        for (int i = 0; i < 3; i++)
            jobs.j[ji++] = {lv_mp_w + (size_t)i * HID * HID, HID, P_300, OFF_LV_MP + i * 51200};
        jobs.j[ji++] = {lv_au_w, 2 * HID, P_AU_MLV, OFF_LV_AU};
        k_splitw_all<<<dim3(320, 15), P_AU_MLV>>>(jobs, wh, wl);
    }

    // ================= t conv (z = 1) =================
    {
        dim3 gE(5, N_EDGES / 128, 1);
        dim3 gN(5, N_NODES / 128, 1);
        float* ha = h;
        float* hb = h2;

        // lin: A = [x[src], ea], K=147, pitch 80
        k_catsplit<<<dim3(N_EDGES / 4, 1), dim3(P_LIN_T, 4)>>>(
            x, edge_attr, ah0, al0, x, edge_attr, ah0, al0,
            src, NODE_DIM + EDGE_DIM, NODE_DIM, EDGE_DIM, P_LIN_T);
        k_gemm<true, false><<<gE, 256, DSMB>>>(
            ah0, al0, nullptr, ha, t_lin_b, OFF_T_LIN,
            ah0, al0, nullptr, ha, t_lin_b, OFF_T_LIN,
            wh, wl, P_LIN_T, 5);

        // CSR build (needed by first segagg)
        k_scan2<<<2, 1024>>>(deg, rowptr, cursor, gcnt, gptr);
        k_fill_csr<<<(N_EDGES + TPB - 1) / TPB, TPB>>>(dst, cursor, eidx, N_EDGES);

        for (int i = 0; i < 3; i++) {
            k_segagg<<<dim3(N_NODES / 2, 1), 320>>>(
                ha, ah0, al0, ha, ah0, al0, rowptr, eidx);
            k_gemm<true, true><<<gE, 256, DSMB>>>(
                ah0, al0, ha, hb, t_mp_b + (size_t)i * HID, OFF_T_MP + i * 51200,
                ah0, al0, ha, hb, t_mp_b + (size_t)i * HID, OFF_T_MP + i * 51200,
                wh, wl, P_300, 10);
            float* t = ha; ha = hb; hb = t;
        }

        k_segsum<<<dim3(N_NODES / 2, 1), 320>>>(ha, nacc, ha, nacc, rowptr, eidx);
        k_catsplit<<<dim3(N_NODES / 2, 1), dim3(P_AU_T, 2)>>>(
            x, nacc, ah0, al0, x, nacc, ah0, al0,
            nullptr, NODE_DIM + HID, NODE_DIM, HID, P_AU_T);
        k_gemm<true, false><<<gN, 256, DSMB>>>(
            ah0, al0, nullptr, shrd, t_au_b, OFF_T_AU,
            ah0, al0, nullptr, shrd, t_au_b, OFF_T_AU,
            wh, wl, P_AU_T, 14);
    }

    // ================= mu + lv convs (fused, z = 2) =================
    {
        dim3 gE(5, N_EDGES / 128, 2);
        dim3 gN(5, N_NODES / 128, 2);
        float* ha0 = h;  float* hb0 = h2;   // mu
        float* ha1 = h3; float* hb1 = h4;   // lv

        // lin: A identical for mu and lv -> materialize once
        k_catsplit<<<dim3(N_EDGES / 2, 1), dim3(P_300, 2)>>>(
            shrd, edge_attr, ah0, al0, shrd, edge_attr, ah0, al0,
            src, HID + EDGE_DIM, HID, EDGE_DIM, P_300);
        k_gemm<true, false><<<gE, 256, DSMB>>>(
            ah0, al0, nullptr, ha0, mu_lin_b, OFF_MU_LIN,
            ah0, al0, nullptr, ha1, lv_lin_b, OFF_LV_LIN,
            wh, wl, P_300, 10);

        for (int i = 0; i < 3; i++) {
            k_segagg<<<dim3(N_NODES / 2, 2), 320>>>(
                ha0, ah0, al0, ha1, ah1, al1, rowptr, eidx);
            k_gemm<true, true><<<gE, 256, DSMB>>>(
                ah0, al0, ha0, hb0, mu_mp_b + (size_t)i * HID, OFF_MU_MP + i * 51200,
                ah1, al1, ha1, hb1, lv_mp_b + (size_t)i * HID, OFF_LV_MP + i * 51200,
                wh, wl, P_300, 10);
            float* t0 = ha0; ha0 = hb0; hb0 = t0;
            float* t1 = ha1; ha1 = hb1; hb1 = t1;
        }

        k_segsum<<<dim3(N_NODES / 2, 2), 320>>>(ha0, nacc, ha1, nacc2, rowptr, eidx);
        k_catsplit<<<dim3(N_NODES / 2, 2), dim3(P_AU_MLV, 2)>>>(
            shrd, nacc, ah0, al0, shrd, nacc2, ah1, al1,
            nullptr, 2 * HID, HID, HID, P_AU_MLV);
        k_gemm<false, false><<<gN, 256, DSMB>>>(
            ah0, al0, nullptr, mu, mu_au_b, OFF_MU_AU,
            ah1, al1, nullptr, lv, lv_au_b, OFF_LV_AU,
            wh, wl, P_AU_MLV, 19);
    }

    k_pool<<<N_GRAPHS, 320>>>(mu, lv, W_atoms, eps, gptr, out);
}